// round 7
// baseline (speedup 1.0000x reference)
#include <cuda_runtime.h>
#include <cuda_bf16.h>
#include <cstdint>

#define TM       64
#define THREADS  256
#define IN_DIM   472
#define HID      128

#define AKS      264                    // padded k-stride (elems) per 256-k half
#define A_HI_OFF 0
#define A_LO_OFF (TM * AKS * 2)         // 33792
#define W_OFF    (2 * TM * AKS * 2)     // 67584
#define WN_STRIDE   80                  // bytes per n-row (64B data + 16B pad), 16-aligned
#define WHL_STRIDE  (128 * WN_STRIDE)   // 10240: hi -> lo
#define WBUF_STRIDE (2 * WHL_STRIDE)    // 20480: one 32-k chunk (hi+lo)
#define MISC     (W_OFF + 2 * WBUF_STRIDE)   // 108544
#define TW_OFF   (MISC)
#define TB_OFF   (MISC + 400)
#define B1_OFF   (MISC + 800)
#define W2_OFF   (MISC + 1312)
#define SRC_OFF  (MISC + 1824)
#define DST_OFF  (MISC + 2080)
#define DT_OFF   (MISC + 2336)
#define PART_OFF (MISC + 2592)
#define SMEM_BYTES (PART_OFF + 4 * TM * 4)   // 112160

__device__ __align__(16) unsigned char g_w[262144];  // [hi|lo][128 n][512 k] bf16

// ---------------- helpers ----------------
__device__ __forceinline__ uint32_t smem_u32(const void* p) {
    uint32_t a;
    asm("{ .reg .u64 t; cvta.to.shared.u64 t, %1; cvt.u32.u64 %0, t; }" : "=r"(a) : "l"(p));
    return a;
}
__device__ __forceinline__ void ldsm4(uint32_t* r, uint32_t a) {
    asm volatile("ldmatrix.sync.aligned.m8n8.x4.shared.b16 {%0,%1,%2,%3}, [%4];"
        : "=r"(r[0]), "=r"(r[1]), "=r"(r[2]), "=r"(r[3]) : "r"(a));
}
__device__ __forceinline__ void mma16816(float* d, const uint32_t* a, uint32_t b0, uint32_t b1) {
    asm volatile("mma.sync.aligned.m16n8k16.row.col.f32.bf16.bf16.f32 "
        "{%0,%1,%2,%3}, {%4,%5,%6,%7}, {%8,%9}, {%0,%1,%2,%3};"
        : "+f"(d[0]), "+f"(d[1]), "+f"(d[2]), "+f"(d[3])
        : "r"(a[0]), "r"(a[1]), "r"(a[2]), "r"(a[3]), "r"(b0), "r"(b1));
}
__device__ __forceinline__ void cpasync16(uint32_t s, const void* g) {
    asm volatile("cp.async.cg.shared.global [%0], [%1], 16;" :: "r"(s), "l"(g) : "memory");
}
#define CP_COMMIT() asm volatile("cp.async.commit_group;" ::: "memory")
#define CP_WAIT0()  asm volatile("cp.async.wait_group 0;" ::: "memory")

// ---------------- W pre-split kernel ----------------
__global__ void wprep_kernel(const float* __restrict__ w1) {
    int i = blockIdx.x * blockDim.x + threadIdx.x;   // 65536
    int n = i >> 9, k = i & 511;
    float v = (k < IN_DIM) ? w1[(size_t)k * HID + n] : 0.f;
    __nv_bfloat16 h = __float2bfloat16(v);
    __nv_bfloat16 l = __float2bfloat16(v - __bfloat162float(h));
    *reinterpret_cast<__nv_bfloat16*>(g_w + ((size_t)n * 512 + k) * 2)          = h;
    *reinterpret_cast<__nv_bfloat16*>(g_w + 131072 + ((size_t)n * 512 + k) * 2) = l;
}

// ---------------- main fused kernel ----------------
__global__ void __launch_bounds__(THREADS, 2)
tgn_kernel(const int* __restrict__ src, const int* __restrict__ dst,
           const float* __restrict__ t, const float* __restrict__ edge_attr,
           const float* __restrict__ memory, const float* __restrict__ last_update,
           const float* __restrict__ time_w, const float* __restrict__ time_b,
           const float* __restrict__ b1, const float* __restrict__ w2,
           const float* __restrict__ b2, float* __restrict__ out, int E)
{
    extern __shared__ char sm[];
    const uint32_t smb = smem_u32(sm);
    const int tid  = threadIdx.x;
    const int wid  = tid >> 5;
    const int lane = tid & 31;
    const int eBase = blockIdx.x * TM;

    float* TW   = (float*)(sm + TW_OFF);
    float* TB   = (float*)(sm + TB_OFF);
    float* B1S  = (float*)(sm + B1_OFF);
    float* W2S  = (float*)(sm + W2_OFF);
    int*   SRCI = (int*)(sm + SRC_OFF);
    int*   DSTI = (int*)(sm + DST_OFF);
    float* DTS  = (float*)(sm + DT_OFF);
    float* PART = (float*)(sm + PART_OFF);

    // ---- W chunk copy: 32 k x 128 n, hi+lo = 16 KB data ----
    auto issueW = [&](int g, int b) {
#pragma unroll
        for (int jj = 0; jj < 4; jj++) {
            int idx = tid + THREADS * jj;       // 0..1023
            int hl = idx >> 9, rem = idx & 511;
            int n = rem >> 2, k4 = rem & 3;
            const char* gs = (const char*)g_w + hl * 131072
                           + ((size_t)n * 512 + g * 32 + k4 * 8) * 2;
            uint32_t sd = smb + W_OFF + b * WBUF_STRIDE + hl * WHL_STRIDE
                        + n * WN_STRIDE + k4 * 16;
            cpasync16(sd, gs);
        }
        CP_COMMIT();
    };
    issueW(0, 0);

    if (tid < 100) { TW[tid] = time_w[tid]; TB[tid] = time_b[tid]; }
    if (tid < HID) { B1S[tid] = b1[tid]; W2S[tid] = w2[tid]; }
    if (tid < TM) {
        int e = eBase + tid;
        int s = 0, d = 0; float dtv = 0.f;
        if (e < E) { s = src[e]; d = dst[e]; dtv = t[e] - last_update[s]; }
        SRCI[tid] = s; DSTI[tid] = d; DTS[tid] = dtv;
    }
    __syncthreads();

    const float2* m2 = reinterpret_cast<const float2*>(memory);
    const float2* e2 = reinterpret_cast<const float2*>(edge_attr);

    // ---- A build: gather + cos + hi/lo split into padded smem ----
    auto buildA = [&](int half) {
        for (int i = tid; i < TM * 128; i += THREADS) {
            int r = i >> 7, j = i & 127;
            float v0 = 0.f, v1 = 0.f;
            if ((eBase + r) < E) {
                if (half == 0) {
                    if (j < 50)       { float2 v = m2[(size_t)SRCI[r] * 50 + j];        v0 = v.x; v1 = v.y; }
                    else if (j < 100) { float2 v = m2[(size_t)DSTI[r] * 50 + (j - 50)]; v0 = v.x; v1 = v.y; }
                    else              { int tk = (j - 100) * 2; float dtv = DTS[r];
                                        v0 = cosf(fmaf(dtv, TW[tk], TB[tk]));
                                        v1 = cosf(fmaf(dtv, TW[tk + 1], TB[tk + 1])); }
                } else {
                    if (j < 22)       { int tk = 56 + j * 2; float dtv = DTS[r];
                                        v0 = cosf(fmaf(dtv, TW[tk], TB[tk]));
                                        v1 = cosf(fmaf(dtv, TW[tk + 1], TB[tk + 1])); }
                    else if (j < 108) { float2 v = e2[(size_t)(eBase + r) * 86 + (j - 22)]; v0 = v.x; v1 = v.y; }
                    // else zero pad (global k 472..511)
                }
            }
            __nv_bfloat16 h0 = __float2bfloat16(v0), h1 = __float2bfloat16(v1);
            __nv_bfloat16 l0 = __float2bfloat16(v0 - __bfloat162float(h0));
            __nv_bfloat16 l1 = __float2bfloat16(v1 - __bfloat162float(h1));
            __nv_bfloat162 hv; hv.x = h0; hv.y = h1;
            __nv_bfloat162 lv; lv.x = l0; lv.y = l1;
            uint32_t off = (uint32_t)r * (AKS * 2) + (uint32_t)j * 4;
            *reinterpret_cast<__nv_bfloat162*>(sm + A_HI_OFF + off) = hv;
            *reinterpret_cast<__nv_bfloat162*>(sm + A_LO_OFF + off) = lv;
        }
    };
    buildA(0);

    // ---- warp tile coordinates: 8 warps = 2 row-groups x 4 col-groups ----
    const int rm = (wid & 1) * 32;
    const int cn = (wid >> 1) * 32;
    const uint32_t aBase = smb + (uint32_t)(rm + (lane & 15)) * (AKS * 2)
                         + (uint32_t)((lane >> 4) << 4);
    const uint32_t bRow  = (uint32_t)(cn + ((lane >> 4) << 3) + (lane & 7)) * WN_STRIDE
                         + (uint32_t)(((lane >> 3) & 1) << 4);

    float acc[2][4][4];
#pragma unroll
    for (int ma = 0; ma < 2; ma++)
#pragma unroll
        for (int na = 0; na < 4; na++)
#pragma unroll
            for (int q = 0; q < 4; q++) acc[ma][na][q] = 0.f;

    // ---- 16 chunks of 32 k; W double-buffered via cp.async ----
    for (int g = 0; g < 16; g++) {
        int buf = g & 1;
        int c = g & 7;
        CP_WAIT0();
        __syncthreads();                 // W[buf] ready; mma(g-1) on buf^1 done
        if (g < 15) issueW(g + 1, buf ^ 1);
        if (g == 8) { buildA(1); __syncthreads(); }

        const uint32_t bBase = smb + W_OFF + (uint32_t)buf * WBUF_STRIDE + bRow;
#pragma unroll
        for (int ks = 0; ks < 2; ks++) {
            uint32_t kb2 = (uint32_t)(c * 32 + ks * 16) * 2;
            uint32_t ah[8], al[8], bh[8], bl[8];
            ldsm4(ah,     aBase + kb2);
            ldsm4(ah + 4, aBase + 16 * (AKS * 2) + kb2);
            ldsm4(al,     aBase + A_LO_OFF + kb2);
            ldsm4(al + 4, aBase + A_LO_OFF + 16 * (AKS * 2) + kb2);
            ldsm4(bh,     bBase + ks * 32);
            ldsm4(bh + 4, bBase + 16 * WN_STRIDE + ks * 32);
            ldsm4(bl,     bBase + WHL_STRIDE + ks * 32);
            ldsm4(bl + 4, bBase + WHL_STRIDE + 16 * WN_STRIDE + ks * 32);
#pragma unroll
            for (int ma = 0; ma < 2; ma++)
#pragma unroll
                for (int na = 0; na < 4; na++) {
                    float* d = acc[ma][na];
                    mma16816(d, ah + ma * 4, bh[na * 2], bh[na * 2 + 1]);
                    mma16816(d, ah + ma * 4, bl[na * 2], bl[na * 2 + 1]);
                    mma16816(d, al + ma * 4, bh[na * 2], bh[na * 2 + 1]);
                }
        }
    }

    // ---- epilogue: bias + ReLU + w2 dot, reduce over n ----
    float p[2][2] = {{0.f, 0.f}, {0.f, 0.f}};
#pragma unroll
    for (int ma = 0; ma < 2; ma++)
#pragma unroll
        for (int na = 0; na < 4; na++) {
            int n0 = cn + na * 8 + ((lane & 3) << 1);
            float b1a = B1S[n0], b1b = B1S[n0 + 1];
            float w2a = W2S[n0], w2b = W2S[n0 + 1];
            float* d = acc[ma][na];
            p[ma][0] += fmaxf(d[0] + b1a, 0.f) * w2a + fmaxf(d[1] + b1b, 0.f) * w2b;
            p[ma][1] += fmaxf(d[2] + b1a, 0.f) * w2a + fmaxf(d[3] + b1b, 0.f) * w2b;
        }
#pragma unroll
    for (int ma = 0; ma < 2; ma++)
#pragma unroll
        for (int rh = 0; rh < 2; rh++) {
            p[ma][rh] += __shfl_xor_sync(0xffffffffu, p[ma][rh], 1);
            p[ma][rh] += __shfl_xor_sync(0xffffffffu, p[ma][rh], 2);
        }
    if ((lane & 3) == 0) {
        int cw = wid >> 1;
        int r0 = rm + (lane >> 2);
        PART[cw * TM + r0]      = p[0][0];
        PART[cw * TM + r0 + 8]  = p[0][1];
        PART[cw * TM + r0 + 16] = p[1][0];
        PART[cw * TM + r0 + 24] = p[1][1];
    }
    __syncthreads();

    if (tid < TM) {
        int e = eBase + tid;
        if (e < E)
            out[e] = PART[tid] + PART[TM + tid] + PART[2 * TM + tid] + PART[3 * TM + tid] + b2[0];
    }
}

extern "C" void kernel_launch(void* const* d_in, const int* in_sizes, int n_in,
                              void* d_out, int out_size)
{
    const int*   src         = (const int*)  d_in[0];
    const int*   dst         = (const int*)  d_in[1];
    const float* t           = (const float*)d_in[2];
    const float* edge_attr   = (const float*)d_in[3];
    const float* memory      = (const float*)d_in[4];
    const float* last_update = (const float*)d_in[5];
    const float* time_w      = (const float*)d_in[6];
    const float* time_b      = (const float*)d_in[7];
    const float* w1          = (const float*)d_in[8];
    const float* b1          = (const float*)d_in[9];
    const float* w2          = (const float*)d_in[10];
    const float* b2          = (const float*)d_in[11];
    float* out = (float*)d_out;

    const int E = in_sizes[0];

    wprep_kernel<<<128, 512>>>(w1);

    cudaFuncSetAttribute(tgn_kernel, cudaFuncAttributeMaxDynamicSharedMemorySize, SMEM_BYTES);
    int grid = (E + TM - 1) / TM;
    tgn_kernel<<<grid, THREADS, SMEM_BYTES>>>(
        src, dst, t, edge_attr, memory, last_update,
        time_w, time_b, b1, w2, b2, out, E);
}

// round 8
// speedup vs baseline: 1.7247x; 1.7247x over previous
#include <cuda_runtime.h>
#include <cuda_fp16.h>
#include <cstdint>

#define TM       64
#define THREADS  256
#define IN_DIM   472
#define HID      128

#define AKS      264                    // padded k-stride (elems) per 256-k half
#define A_OFF    0
#define W_OFF    (TM * AKS * 2)         // 33792
#define WN_STRIDE   80                  // bytes per n-row (64B data + 16B pad), 16-aligned
#define WBUF_STRIDE (128 * WN_STRIDE)   // 10240: one 32-k chunk
#define MISC     (W_OFF + 2 * WBUF_STRIDE)   // 54272
#define TW_OFF   (MISC)
#define TB_OFF   (MISC + 400)
#define B1_OFF   (MISC + 800)
#define W2_OFF   (MISC + 1312)
#define SRC_OFF  (MISC + 1824)
#define DST_OFF  (MISC + 2080)
#define DT_OFF   (MISC + 2336)
#define PART_OFF (MISC + 2592)
#define SMEM_BYTES (PART_OFF + 4 * TM * 4)   // 57888  (x3 CTA = 173664 <= 228KB)

__device__ __align__(16) __half g_w[128 * 512];   // [n][k] fp16, 128 KB

// ---------------- helpers ----------------
__device__ __forceinline__ uint32_t smem_u32(const void* p) {
    uint32_t a;
    asm("{ .reg .u64 t; cvta.to.shared.u64 t, %1; cvt.u32.u64 %0, t; }" : "=r"(a) : "l"(p));
    return a;
}
__device__ __forceinline__ void ldsm4(uint32_t* r, uint32_t a) {
    asm volatile("ldmatrix.sync.aligned.m8n8.x4.shared.b16 {%0,%1,%2,%3}, [%4];"
        : "=r"(r[0]), "=r"(r[1]), "=r"(r[2]), "=r"(r[3]) : "r"(a));
}
__device__ __forceinline__ void mma16816(float* d, const uint32_t* a, uint32_t b0, uint32_t b1) {
    asm volatile("mma.sync.aligned.m16n8k16.row.col.f32.f16.f16.f32 "
        "{%0,%1,%2,%3}, {%4,%5,%6,%7}, {%8,%9}, {%0,%1,%2,%3};"
        : "+f"(d[0]), "+f"(d[1]), "+f"(d[2]), "+f"(d[3])
        : "r"(a[0]), "r"(a[1]), "r"(a[2]), "r"(a[3]), "r"(b0), "r"(b1));
}
__device__ __forceinline__ void cpasync16(uint32_t s, const void* g) {
    asm volatile("cp.async.cg.shared.global [%0], [%1], 16;" :: "r"(s), "l"(g) : "memory");
}
#define CP_COMMIT() asm volatile("cp.async.commit_group;" ::: "memory")
#define CP_WAIT0()  asm volatile("cp.async.wait_group 0;" ::: "memory")

// ---------------- W prep kernel: fp32 -> fp16, [n][k] ----------------
__global__ void wprep_kernel(const float* __restrict__ w1) {
    int i = blockIdx.x * blockDim.x + threadIdx.x;   // 65536
    int n = i >> 9, k = i & 511;
    float v = (k < IN_DIM) ? w1[(size_t)k * HID + n] : 0.f;
    g_w[(size_t)n * 512 + k] = __float2half(v);
}

// ---------------- main fused kernel ----------------
__global__ void __launch_bounds__(THREADS, 3)
tgn_kernel(const int* __restrict__ src, const int* __restrict__ dst,
           const float* __restrict__ t, const float* __restrict__ edge_attr,
           const float* __restrict__ memory, const float* __restrict__ last_update,
           const float* __restrict__ time_w, const float* __restrict__ time_b,
           const float* __restrict__ b1, const float* __restrict__ w2,
           const float* __restrict__ b2, float* __restrict__ out, int E)
{
    extern __shared__ char sm[];
    const uint32_t smb = smem_u32(sm);
    const int tid  = threadIdx.x;
    const int wid  = tid >> 5;
    const int lane = tid & 31;
    const int eBase = blockIdx.x * TM;

    float* TW   = (float*)(sm + TW_OFF);
    float* TB   = (float*)(sm + TB_OFF);
    float* B1S  = (float*)(sm + B1_OFF);
    float* W2S  = (float*)(sm + W2_OFF);
    int*   SRCI = (int*)(sm + SRC_OFF);
    int*   DSTI = (int*)(sm + DST_OFF);
    float* DTS  = (float*)(sm + DT_OFF);
    float* PART = (float*)(sm + PART_OFF);

    // ---- W chunk copy: 32 k x 128 n fp16 = 8 KB ----
    auto issueW = [&](int g, int b) {
#pragma unroll
        for (int jj = 0; jj < 2; jj++) {
            int idx = tid + THREADS * jj;       // 0..511
            int n = idx >> 2, k4 = idx & 3;
            const char* gs = (const char*)g_w + ((size_t)n * 512 + g * 32 + k4 * 8) * 2;
            uint32_t sd = smb + W_OFF + b * WBUF_STRIDE + n * WN_STRIDE + k4 * 16;
            cpasync16(sd, gs);
        }
        CP_COMMIT();
    };
    issueW(0, 0);

    if (tid < 100) { TW[tid] = time_w[tid]; TB[tid] = time_b[tid]; }
    if (tid < HID) { B1S[tid] = b1[tid]; W2S[tid] = w2[tid]; }
    if (tid < TM) {
        int e = eBase + tid;
        int s = 0, d = 0; float dtv = 0.f;
        if (e < E) { s = src[e]; d = dst[e]; dtv = t[e] - last_update[s]; }
        SRCI[tid] = s; DSTI[tid] = d; DTS[tid] = dtv;
    }
    __syncthreads();

    const float2* m2 = reinterpret_cast<const float2*>(memory);
    const float2* e2 = reinterpret_cast<const float2*>(edge_attr);

    // ---- A build: gather + cos -> fp16, padded smem ----
    auto buildA = [&](int half) {
        for (int i = tid; i < TM * 128; i += THREADS) {
            int r = i >> 7, j = i & 127;
            float v0 = 0.f, v1 = 0.f;
            if ((eBase + r) < E) {
                if (half == 0) {
                    if (j < 50)       { float2 v = m2[(size_t)SRCI[r] * 50 + j];        v0 = v.x; v1 = v.y; }
                    else if (j < 100) { float2 v = m2[(size_t)DSTI[r] * 50 + (j - 50)]; v0 = v.x; v1 = v.y; }
                    else              { int tk = (j - 100) * 2; float dtv = DTS[r];
                                        v0 = cosf(fmaf(dtv, TW[tk], TB[tk]));
                                        v1 = cosf(fmaf(dtv, TW[tk + 1], TB[tk + 1])); }
                } else {
                    if (j < 22)       { int tk = 56 + j * 2; float dtv = DTS[r];
                                        v0 = cosf(fmaf(dtv, TW[tk], TB[tk]));
                                        v1 = cosf(fmaf(dtv, TW[tk + 1], TB[tk + 1])); }
                    else if (j < 108) { float2 v = e2[(size_t)(eBase + r) * 86 + (j - 22)]; v0 = v.x; v1 = v.y; }
                    // else zero pad (global k 472..511)
                }
            }
            __half2 hv; hv.x = __float2half(v0); hv.y = __float2half(v1);
            uint32_t off = (uint32_t)r * (AKS * 2) + (uint32_t)j * 4;
            *reinterpret_cast<__half2*>(sm + A_OFF + off) = hv;
        }
    };
    buildA(0);

    // ---- warp tile coordinates: 8 warps = 2 row-groups x 4 col-groups ----
    const int rm = (wid & 1) * 32;
    const int cn = (wid >> 1) * 32;
    const uint32_t aBase = smb + A_OFF + (uint32_t)(rm + (lane & 15)) * (AKS * 2)
                         + (uint32_t)((lane >> 4) << 4);
    const uint32_t bRow  = (uint32_t)(cn + ((lane >> 4) << 3) + (lane & 7)) * WN_STRIDE
                         + (uint32_t)(((lane >> 3) & 1) << 4);

    float acc[2][4][4];
#pragma unroll
    for (int ma = 0; ma < 2; ma++)
#pragma unroll
        for (int na = 0; na < 4; na++)
#pragma unroll
            for (int q = 0; q < 4; q++) acc[ma][na][q] = 0.f;

    // ---- 16 chunks of 32 k; W double-buffered via cp.async ----
    for (int g = 0; g < 16; g++) {
        int buf = g & 1;
        int c = g & 7;
        CP_WAIT0();
        __syncthreads();                 // W[buf] ready; mma(g-1) on buf^1 done
        if (g < 15) issueW(g + 1, buf ^ 1);
        if (g == 8) { buildA(1); __syncthreads(); }

        const uint32_t bBase = smb + W_OFF + (uint32_t)buf * WBUF_STRIDE + bRow;
#pragma unroll
        for (int ks = 0; ks < 2; ks++) {
            uint32_t kb2 = (uint32_t)(c * 32 + ks * 16) * 2;
            uint32_t ah[8], bh[8];
            ldsm4(ah,     aBase + kb2);
            ldsm4(ah + 4, aBase + 16 * (AKS * 2) + kb2);
            ldsm4(bh,     bBase + ks * 32);
            ldsm4(bh + 4, bBase + 16 * WN_STRIDE + ks * 32);
#pragma unroll
            for (int ma = 0; ma < 2; ma++)
#pragma unroll
                for (int na = 0; na < 4; na++)
                    mma16816(acc[ma][na], ah + ma * 4, bh[na * 2], bh[na * 2 + 1]);
        }
    }

    // ---- epilogue: bias + ReLU + w2 dot, reduce over n ----
    float p[2][2] = {{0.f, 0.f}, {0.f, 0.f}};
#pragma unroll
    for (int ma = 0; ma < 2; ma++)
#pragma unroll
        for (int na = 0; na < 4; na++) {
            int n0 = cn + na * 8 + ((lane & 3) << 1);
            float b1a = B1S[n0], b1b = B1S[n0 + 1];
            float w2a = W2S[n0], w2b = W2S[n0 + 1];
            float* d = acc[ma][na];
            p[ma][0] += fmaxf(d[0] + b1a, 0.f) * w2a + fmaxf(d[1] + b1b, 0.f) * w2b;
            p[ma][1] += fmaxf(d[2] + b1a, 0.f) * w2a + fmaxf(d[3] + b1b, 0.f) * w2b;
        }
#pragma unroll
    for (int ma = 0; ma < 2; ma++)
#pragma unroll
        for (int rh = 0; rh < 2; rh++) {
            p[ma][rh] += __shfl_xor_sync(0xffffffffu, p[ma][rh], 1);
            p[ma][rh] += __shfl_xor_sync(0xffffffffu, p[ma][rh], 2);
        }
    if ((lane & 3) == 0) {
        int cw = wid >> 1;
        int r0 = rm + (lane >> 2);
        PART[cw * TM + r0]      = p[0][0];
        PART[cw * TM + r0 + 8]  = p[0][1];
        PART[cw * TM + r0 + 16] = p[1][0];
        PART[cw * TM + r0 + 24] = p[1][1];
    }
    __syncthreads();

    if (tid < TM) {
        int e = eBase + tid;
        if (e < E)
            out[e] = PART[tid] + PART[TM + tid] + PART[2 * TM + tid] + PART[3 * TM + tid] + b2[0];
    }
}

extern "C" void kernel_launch(void* const* d_in, const int* in_sizes, int n_in,
                              void* d_out, int out_size)
{
    const int*   src         = (const int*)  d_in[0];
    const int*   dst         = (const int*)  d_in[1];
    const float* t           = (const float*)d_in[2];
    const float* edge_attr   = (const float*)d_in[3];
    const float* memory      = (const float*)d_in[4];
    const float* last_update = (const float*)d_in[5];
    const float* time_w      = (const float*)d_in[6];
    const float* time_b      = (const float*)d_in[7];
    const float* w1          = (const float*)d_in[8];
    const float* b1          = (const float*)d_in[9];
    const float* w2          = (const float*)d_in[10];
    const float* b2          = (const float*)d_in[11];
    float* out = (float*)d_out;

    const int E = in_sizes[0];

    wprep_kernel<<<128, 512>>>(w1);

    cudaFuncSetAttribute(tgn_kernel, cudaFuncAttributeMaxDynamicSharedMemorySize, SMEM_BYTES);
    int grid = (E + TM - 1) / TM;
    tgn_kernel<<<grid, THREADS, SMEM_BYTES>>>(
        src, dst, t, edge_attr, memory, last_update,
        time_w, time_b, b1, w2, b2, out, E);
}